// round 1
// baseline (speedup 1.0000x reference)
#include <cuda_runtime.h>
#include <math.h>

#define N_   8192
#define D_   2048
#define P_   512
#define EPSF 1e-12f

// ---------------- scratch (device globals; no allocation allowed) ----------
__device__ int   g_count[P_];
__device__ int   g_offset[P_];
__device__ int   g_cursor[P_];
__device__ int   g_members[N_];
__device__ float g_centers[3][P_][D_];   // unit centers, fp32
__device__ float g_cnorm[3 * P_];        // ||sum_c|| per (modality, class)
__device__ float g_logits[3][P_][P_];    // un-scaled dot products c1 . c2
__device__ float g_rowloss[3 * P_];

// ---------------- helpers --------------------------------------------------
__device__ __forceinline__ float warpSum(float v) {
#pragma unroll
    for (int o = 16; o; o >>= 1) v += __shfl_xor_sync(0xffffffffu, v, o);
    return v;
}
__device__ __forceinline__ float warpMax(float v) {
#pragma unroll
    for (int o = 16; o; o >>= 1) v = fmaxf(v, __shfl_xor_sync(0xffffffffu, v, o));
    return v;
}
__device__ __forceinline__ unsigned f2tf32(float x) {
    unsigned r;
    asm("cvt.rna.tf32.f32 %0, %1;" : "=r"(r) : "f"(x));
    return r;
}

// ---------------- kernel 0: member list build ------------------------------
__global__ void k0_zero() {
    int t = blockIdx.x * blockDim.x + threadIdx.x;
    if (t < P_) { g_count[t] = 0; g_cursor[t] = 0; }
}
__global__ void k0_count(const int* __restrict__ label) {
    int i = blockIdx.x * blockDim.x + threadIdx.x;
    if (i < N_) atomicAdd(&g_count[label[i]], 1);
}
__global__ void k0_scan() {
    __shared__ int s[P_];
    int t = threadIdx.x;
    int c = g_count[t];
    s[t] = c;
    __syncthreads();
    for (int d = 1; d < P_; d <<= 1) {
        int v = (t >= d) ? s[t - d] : 0;
        __syncthreads();
        s[t] += v;
        __syncthreads();
    }
    g_offset[t] = s[t] - c;  // exclusive prefix
}
__global__ void k0_fill(const int* __restrict__ label) {
    int i = blockIdx.x * blockDim.x + threadIdx.x;
    if (i < N_) {
        int c = label[i];
        int pos = atomicAdd(&g_cursor[c], 1);
        g_members[g_offset[c] + pos] = i;
    }
}

// ---------------- kernel 1: centers + intra (single feature pass) ----------
// grid (P_, 3), block 256.  Thread t owns float4 columns t and t+256.
__global__ void __launch_bounds__(256) k1_centers(const float* __restrict__ f0,
                                                  const float* __restrict__ f1,
                                                  const float* __restrict__ f2) {
    int c = blockIdx.x, m = blockIdx.y;
    const float* f = (m == 0) ? f0 : ((m == 1) ? f1 : f2);
    int off = g_offset[c];
    int K   = g_count[c];
    int t   = threadIdx.x;

    __shared__ float wred[8];
    __shared__ float bcast;

    float a0 = 0.f, a1 = 0.f, a2 = 0.f, a3 = 0.f;
    float a4 = 0.f, a5 = 0.f, a6 = 0.f, a7 = 0.f;

    for (int k = 0; k < K; k++) {
        int row = g_members[off + k];
        const float4* r = (const float4*)(f + (size_t)row * D_);
        float4 x = __ldg(&r[t]);
        float4 y = __ldg(&r[t + 256]);
        float ss = x.x * x.x + x.y * x.y + x.z * x.z + x.w * x.w
                 + y.x * y.x + y.y * y.y + y.z * y.z + y.w * y.w;
        ss = warpSum(ss);
        if ((t & 31) == 0) wred[t >> 5] = ss;
        __syncthreads();
        if (t < 32) {
            float v = (t < 8) ? wred[t] : 0.f;
            v = warpSum(v);
            if (t == 0) bcast = v;
        }
        __syncthreads();
        float inv = 1.f / fmaxf(sqrtf(bcast), EPSF);
        a0 += x.x * inv; a1 += x.y * inv; a2 += x.z * inv; a3 += x.w * inv;
        a4 += y.x * inv; a5 += y.y * inv; a6 += y.z * inv; a7 += y.w * inv;
        __syncthreads();  // protect wred/bcast reuse next iteration
    }

    float ss2 = a0 * a0 + a1 * a1 + a2 * a2 + a3 * a3
              + a4 * a4 + a5 * a5 + a6 * a6 + a7 * a7;
    ss2 = warpSum(ss2);
    if ((t & 31) == 0) wred[t >> 5] = ss2;
    __syncthreads();
    if (t < 32) {
        float v = (t < 8) ? wred[t] : 0.f;
        v = warpSum(v);
        if (t == 0) bcast = v;
    }
    __syncthreads();
    float nrm  = sqrtf(bcast);
    float inv2 = 1.f / fmaxf(nrm, EPSF);

    float4* cd = (float4*)&g_centers[m][c][0];
    cd[t]       = make_float4(a0 * inv2, a1 * inv2, a2 * inv2, a3 * inv2);
    cd[t + 256] = make_float4(a4 * inv2, a5 * inv2, a6 * inv2, a7 * inv2);
    if (t == 0) g_cnorm[m * P_ + c] = nrm;
}

// ---------------- kernel 2: three 512x512xK=2048 tf32 mma GEMMs ------------
// grid (8, 8, 3), block 128 (4 warps, 2x2, 32x32 per warp).
// Smem XOR swizzle: element (row, kcol) -> row*32 + (((kcol>>2) ^ (row&7))<<2) + (kcol&3)
__global__ void __launch_bounds__(128) k2_gemm() {
    int p  = blockIdx.z;
    int pa = (p == 2) ? 1 : 0;
    int pb = (p == 0) ? 1 : 2;
    const float* A = &g_centers[pa][0][0];
    const float* B = &g_centers[pb][0][0];

    __shared__ unsigned As[64 * 32];
    __shared__ unsigned Bs[64 * 32];

    int t = threadIdx.x, lane = t & 31, warp = t >> 5;
    int wr = warp >> 1, wc = warp & 1;
    int brow = blockIdx.y * 64, bcol = blockIdx.x * 64;

    float acc[2][4][4];
#pragma unroll
    for (int mt = 0; mt < 2; mt++)
#pragma unroll
        for (int nt = 0; nt < 4; nt++)
#pragma unroll
            for (int e = 0; e < 4; e++) acc[mt][nt][e] = 0.f;

    for (int kc = 0; kc < D_; kc += 32) {
#pragma unroll
        for (int j = 0; j < 4; j++) {
            int i   = t + j * 128;          // 0..511
            int row = i >> 3;
            int c4g = i & 7;
            int soff = row * 32 + ((c4g ^ (row & 7)) << 2);
            float4 va = *(const float4*)(A + (size_t)(brow + row) * D_ + kc + c4g * 4);
            float4 vb = *(const float4*)(B + (size_t)(bcol + row) * D_ + kc + c4g * 4);
            *(uint4*)&As[soff] = make_uint4(f2tf32(va.x), f2tf32(va.y), f2tf32(va.z), f2tf32(va.w));
            *(uint4*)&Bs[soff] = make_uint4(f2tf32(vb.x), f2tf32(vb.y), f2tf32(vb.z), f2tf32(vb.w));
        }
        __syncthreads();

#pragma unroll
        for (int ks = 0; ks < 4; ks++) {
            int g0 = 2 * ks;        // c4 group for k..k+3
            int g1 = 2 * ks + 1;    // c4 group for k+4..k+7
            int r7 = lane >> 2;     // low bits of frag row (bases are 8/16 aligned)
            int e  = lane & 3;

            unsigned a[2][4], b[4][2];
#pragma unroll
            for (int mt = 0; mt < 2; mt++) {
                int r  = wr * 32 + mt * 16 + r7;
                int b0 = r * 32 + e;
                a[mt][0] = As[b0 + ((g0 ^ r7) << 2)];
                a[mt][1] = As[b0 + 8 * 32 + ((g0 ^ r7) << 2)];
                a[mt][2] = As[b0 + ((g1 ^ r7) << 2)];
                a[mt][3] = As[b0 + 8 * 32 + ((g1 ^ r7) << 2)];
            }
#pragma unroll
            for (int nt = 0; nt < 4; nt++) {
                int n  = wc * 32 + nt * 8 + r7;
                int b0 = n * 32 + e;
                b[nt][0] = Bs[b0 + ((g0 ^ r7) << 2)];
                b[nt][1] = Bs[b0 + ((g1 ^ r7) << 2)];
            }
#pragma unroll
            for (int mt = 0; mt < 2; mt++)
#pragma unroll
                for (int nt = 0; nt < 4; nt++)
                    asm volatile(
                        "mma.sync.aligned.m16n8k8.row.col.f32.tf32.tf32.f32 "
                        "{%0,%1,%2,%3},{%4,%5,%6,%7},{%8,%9},{%0,%1,%2,%3};"
                        : "+f"(acc[mt][nt][0]), "+f"(acc[mt][nt][1]),
                          "+f"(acc[mt][nt][2]), "+f"(acc[mt][nt][3])
                        : "r"(a[mt][0]), "r"(a[mt][1]), "r"(a[mt][2]), "r"(a[mt][3]),
                          "r"(b[nt][0]), "r"(b[nt][1]));
        }
        __syncthreads();
    }

    float* C = &g_logits[p][0][0];
#pragma unroll
    for (int mt = 0; mt < 2; mt++)
#pragma unroll
        for (int nt = 0; nt < 4; nt++) {
            int row = brow + wr * 32 + mt * 16 + (lane >> 2);
            int col = bcol + wc * 32 + nt * 8 + (lane & 3) * 2;
            *(float2*)(C + (size_t)row * P_ + col)       = make_float2(acc[mt][nt][0], acc[mt][nt][1]);
            *(float2*)(C + (size_t)(row + 8) * P_ + col) = make_float2(acc[mt][nt][2], acc[mt][nt][3]);
        }
}

// ---------------- kernel 3a: per-row log-sum-exp ---------------------------
// grid (P_, 3), block 128. logits scaled by 1/TAU = 2 here.
__global__ void __launch_bounds__(128) k3_row() {
    int i = blockIdx.x, p = blockIdx.y;
    const float* row = &g_logits[p][i][0];
    int t = threadIdx.x;

    float v0 = row[t] * 2.f, v1 = row[t + 128] * 2.f;
    float v2 = row[t + 256] * 2.f, v3 = row[t + 384] * 2.f;

    __shared__ float wred[4];
    __shared__ float bc;

    float mx = fmaxf(fmaxf(v0, v1), fmaxf(v2, v3));
    mx = warpMax(mx);
    if ((t & 31) == 0) wred[t >> 5] = mx;
    __syncthreads();
    if (t < 32) {
        float m2 = (t < 4) ? wred[t] : -3.0e38f;
        m2 = warpMax(m2);
        if (t == 0) bc = m2;
    }
    __syncthreads();
    float M = bc;

    float es = __expf(v0 - M) + __expf(v1 - M) + __expf(v2 - M) + __expf(v3 - M);
    es = warpSum(es);
    __syncthreads();
    if ((t & 31) == 0) wred[t >> 5] = es;
    __syncthreads();
    if (t == 0) {
        float S = wred[0] + wred[1] + wred[2] + wred[3];
        float lse = M + __logf(S);
        g_rowloss[p * P_ + i] = lse - row[i] * 2.f;
    }
}

// ---------------- kernel 3b: final scalar ----------------------------------
__global__ void k3_final(float* __restrict__ out) {
    int t = threadIdx.x;  // 512 threads
    float rl = g_rowloss[t] + g_rowloss[t + 512] + g_rowloss[t + 1024];
    float cn = g_cnorm[t]   + g_cnorm[t + 512]   + g_cnorm[t + 1024];
    __shared__ float w1[16], w2[16];
    rl = warpSum(rl);
    cn = warpSum(cn);
    if ((t & 31) == 0) { w1[t >> 5] = rl; w2[t >> 5] = cn; }
    __syncthreads();
    if (t == 0) {
        float R = 0.f, C = 0.f;
        for (int i = 0; i < 16; i++) { R += w1[i]; C += w2[i]; }
        // loss_intra = sum_m (2 - (2/N) sum_c ||s_c||) = 6 - (2/N)*C
        // loss_inter = sum over all 3*P rows of (lse - diag) / P
        out[0] = 6.f - (2.f / (float)N_) * C + R / (float)P_;
    }
}

// ---------------- launch ----------------------------------------------------
extern "C" void kernel_launch(void* const* d_in, const int* in_sizes, int n_in,
                              void* d_out, int out_size) {
    const float* fv    = (const float*)d_in[0];
    const float* fa    = (const float*)d_in[1];
    const float* fr    = (const float*)d_in[2];
    const int*   label = (const int*)d_in[3];
    (void)in_sizes; (void)n_in; (void)out_size;

    k0_zero<<<2, 256>>>();
    k0_count<<<N_ / 256, 256>>>(label);
    k0_scan<<<1, P_>>>();
    k0_fill<<<N_ / 256, 256>>>(label);
    k1_centers<<<dim3(P_, 3), 256>>>(fv, fa, fr);
    k2_gemm<<<dim3(8, 8, 3), 128>>>();
    k3_row<<<dim3(P_, 3), 128>>>();
    k3_final<<<1, P_>>>((float*)d_out);
}

// round 3
// speedup vs baseline: 1.6082x; 1.6082x over previous
#include <cuda_runtime.h>
#include <cuda_bf16.h>
#include <math.h>

#define N_   8192
#define D_   2048
#define P_   512
#define EPSF 1e-12f

// ---------------- scratch (device globals; no allocation allowed) ----------
__device__ int   g_count[P_];
__device__ int   g_offset[P_];
__device__ int   g_members[N_];
__device__ __nv_bfloat16 g_cbf[3][P_][D_];   // unit centers, bf16 (GEMM operands)
__device__ float g_cnorm[3 * P_];            // ||sum_c|| per (modality, class)
__device__ float g_logits[3][P_][P_];        // un-scaled dot products
__device__ float g_rowloss[3 * P_];

// ---------------- helpers --------------------------------------------------
__device__ __forceinline__ float warpSum(float v) {
#pragma unroll
    for (int o = 16; o; o >>= 1) v += __shfl_xor_sync(0xffffffffu, v, o);
    return v;
}
__device__ __forceinline__ float warpMax(float v) {
#pragma unroll
    for (int o = 16; o; o >>= 1) v = fmaxf(v, __shfl_xor_sync(0xffffffffu, v, o));
    return v;
}
__device__ __forceinline__ unsigned bfpack(float lo, float hi) {
    unsigned a = (unsigned)__bfloat16_as_ushort(__float2bfloat16_rn(lo));
    unsigned b = (unsigned)__bfloat16_as_ushort(__float2bfloat16_rn(hi));
    return a | (b << 16);
}

// ---------------- kernel 0: member list build (single block) ----------------
__global__ void __launch_bounds__(1024) k0_all(const int* __restrict__ label) {
    __shared__ int cnt[P_], off[P_];
    int t = threadIdx.x;
    if (t < P_) cnt[t] = 0;
    __syncthreads();
    for (int i = t; i < N_; i += 1024) atomicAdd(&cnt[label[i]], 1);
    __syncthreads();
    if (t < P_) off[t] = cnt[t];
    __syncthreads();
    for (int d = 1; d < P_; d <<= 1) {
        int v = 0;
        if (t < P_ && t >= d) v = off[t - d];
        __syncthreads();
        if (t < P_) off[t] += v;
        __syncthreads();
    }
    if (t < P_) {
        int exc = off[t] - cnt[t];
        g_count[t]  = cnt[t];
        g_offset[t] = exc;
        cnt[t] = exc;  // reuse as write cursor
    }
    __syncthreads();
    for (int i = t; i < N_; i += 1024) {
        int c = label[i];
        int pos = atomicAdd(&cnt[c], 1);
        g_members[pos] = i;
    }
}

// ---------------- kernel 1: centers + intra (single pass, pipelined) -------
// grid (P_, 3), block 256. Thread t owns float4 granules t and t+256.
__global__ void __launch_bounds__(256) k1_centers(const float* __restrict__ f0,
                                                  const float* __restrict__ f1,
                                                  const float* __restrict__ f2) {
    int c = blockIdx.x, m = blockIdx.y;
    const float* f = (m == 0) ? f0 : ((m == 1) ? f1 : f2);
    int off = g_offset[c];
    int K   = g_count[c];
    int t   = threadIdx.x, w = t >> 5, lane = t & 31;

    __shared__ float wred[2][8];

    float a0 = 0.f, a1 = 0.f, a2 = 0.f, a3 = 0.f;
    float a4 = 0.f, a5 = 0.f, a6 = 0.f, a7 = 0.f;

    // prologue load (row 0)
    int row = g_members[off];
    const float4* r0p = (const float4*)(f + (size_t)row * D_);
    float4 x = __ldg(&r0p[t]);
    float4 y = __ldg(&r0p[t + 256]);

    for (int k = 0; k < K; k++) {
        float4 xn = make_float4(0.f, 0.f, 0.f, 0.f), yn = xn;
        if (k + 1 < K) {  // prefetch next row: LDG latency overlaps reduction
            int rn = g_members[off + k + 1];
            const float4* rp = (const float4*)(f + (size_t)rn * D_);
            xn = __ldg(&rp[t]);
            yn = __ldg(&rp[t + 256]);
        }
        float ss = x.x * x.x + x.y * x.y + x.z * x.z + x.w * x.w
                 + y.x * y.x + y.y * y.y + y.z * y.z + y.w * y.w;
        ss = warpSum(ss);
        if (lane == 0) wred[k & 1][w] = ss;
        __syncthreads();  // single barrier per row (double-buffered partials)
        float tot = wred[k & 1][0] + wred[k & 1][1] + wred[k & 1][2] + wred[k & 1][3]
                  + wred[k & 1][4] + wred[k & 1][5] + wred[k & 1][6] + wred[k & 1][7];
        float inv = 1.f / fmaxf(sqrtf(tot), EPSF);
        a0 += x.x * inv; a1 += x.y * inv; a2 += x.z * inv; a3 += x.w * inv;
        a4 += y.x * inv; a5 += y.y * inv; a6 += y.z * inv; a7 += y.w * inv;
        x = xn; y = yn;
    }

    float ss2 = a0 * a0 + a1 * a1 + a2 * a2 + a3 * a3
              + a4 * a4 + a5 * a5 + a6 * a6 + a7 * a7;
    ss2 = warpSum(ss2);
    if (lane == 0) wred[0][w] = ss2;
    __syncthreads();
    float tot2 = wred[0][0] + wred[0][1] + wred[0][2] + wred[0][3]
               + wred[0][4] + wred[0][5] + wred[0][6] + wred[0][7];
    float nrm  = sqrtf(tot2);
    float inv2 = 1.f / fmaxf(nrm, EPSF);

    __nv_bfloat16* cb = &g_cbf[m][c][0];
    uint2 u0, u1;
    u0.x = bfpack(a0 * inv2, a1 * inv2); u0.y = bfpack(a2 * inv2, a3 * inv2);
    u1.x = bfpack(a4 * inv2, a5 * inv2); u1.y = bfpack(a6 * inv2, a7 * inv2);
    *(uint2*)(cb + 4 * t)         = u0;
    *(uint2*)(cb + 4 * (t + 256)) = u1;
    if (t == 0) g_cnorm[m * P_ + c] = nrm;
}

// ---------------- kernel 2: three 512x512xK=2048 bf16 mma GEMMs ------------
// grid (8, 8, 3), block 128 (4 warps, 2x2, each warp 32x32).
// smem tile: 64 rows x 64 bf16 (128 B/row); XOR swizzle on 16B granules:
//   byte(row, g) = row*128 + ((g ^ (row & 7)) << 4)
#define KC_ 64
__device__ __forceinline__ unsigned sw_off(int row, int g) {
    return (unsigned)(row * 128 + ((g ^ (row & 7)) << 4));
}

__global__ void __launch_bounds__(128) k2_gemm() {
    int p  = blockIdx.z;
    int pa = (p == 2) ? 1 : 0;
    int pb = (p == 0) ? 1 : 2;
    const __nv_bfloat16* A = &g_cbf[pa][0][0];
    const __nv_bfloat16* B = &g_cbf[pb][0][0];

    __shared__ __align__(16) unsigned char As[64 * 128];
    __shared__ __align__(16) unsigned char Bs[64 * 128];
    unsigned asb = (unsigned)__cvta_generic_to_shared(As);
    unsigned bsb = (unsigned)__cvta_generic_to_shared(Bs);

    int t = threadIdx.x, lane = t & 31, warp = t >> 5;
    int wr = warp >> 1, wc = warp & 1;
    int brow = blockIdx.y * 64, bcol = blockIdx.x * 64;

    float acc[2][4][4];
#pragma unroll
    for (int mt = 0; mt < 2; mt++)
#pragma unroll
        for (int nt = 0; nt < 4; nt++)
#pragma unroll
            for (int e = 0; e < 4; e++) acc[mt][nt][e] = 0.f;

    // ldmatrix row/granule selectors
    int rsel = lane & 15, gsel = lane >> 4;

    uint4 ga[4], gb[4];
    // prologue: gmem chunk 0 -> regs
#pragma unroll
    for (int j = 0; j < 4; j++) {
        int i = t + j * 128, row = i >> 3, g = i & 7;
        ga[j] = *(const uint4*)(A + (size_t)(brow + row) * D_ + g * 8);
        gb[j] = *(const uint4*)(B + (size_t)(bcol + row) * D_ + g * 8);
    }

    for (int kc = 0; kc < D_ / KC_; kc++) {
        // stage regs -> smem
#pragma unroll
        for (int j = 0; j < 4; j++) {
            int i = t + j * 128, row = i >> 3, g = i & 7;
            *(uint4*)(As + sw_off(row, g)) = ga[j];
            *(uint4*)(Bs + sw_off(row, g)) = gb[j];
        }
        __syncthreads();

        // prefetch next gmem chunk (overlaps the mma chain below)
        if (kc + 1 < D_ / KC_) {
            int co = (kc + 1) * KC_;
#pragma unroll
            for (int j = 0; j < 4; j++) {
                int i = t + j * 128, row = i >> 3, g = i & 7;
                ga[j] = *(const uint4*)(A + (size_t)(brow + row) * D_ + co + g * 8);
                gb[j] = *(const uint4*)(B + (size_t)(bcol + row) * D_ + co + g * 8);
            }
        }

#pragma unroll
        for (int kh = 0; kh < 4; kh++) {  // 4 x k16 sub-chunks
            unsigned af[2][4], bfr[2][4];
#pragma unroll
            for (int mt = 0; mt < 2; mt++) {
                unsigned ad = asb + sw_off(wr * 32 + mt * 16 + rsel, kh * 2 + gsel);
                asm volatile("ldmatrix.sync.aligned.m8n8.x4.shared.b16 {%0,%1,%2,%3}, [%4];"
                             : "=r"(af[mt][0]), "=r"(af[mt][1]), "=r"(af[mt][2]), "=r"(af[mt][3])
                             : "r"(ad));
            }
#pragma unroll
            for (int np = 0; np < 2; np++) {
                unsigned bd = bsb + sw_off(wc * 32 + np * 16 + rsel, kh * 2 + gsel);
                asm volatile("ldmatrix.sync.aligned.m8n8.x4.shared.b16 {%0,%1,%2,%3}, [%4];"
                             : "=r"(bfr[np][0]), "=r"(bfr[np][1]), "=r"(bfr[np][2]), "=r"(bfr[np][3])
                             : "r"(bd));
            }
#pragma unroll
            for (int mt = 0; mt < 2; mt++)
#pragma unroll
                for (int nt = 0; nt < 4; nt++) {
                    int np = nt >> 1, s = nt & 1;
                    asm volatile(
                        "mma.sync.aligned.m16n8k16.row.col.f32.bf16.bf16.f32 "
                        "{%0,%1,%2,%3},{%4,%5,%6,%7},{%8,%9},{%0,%1,%2,%3};"
                        : "+f"(acc[mt][nt][0]), "+f"(acc[mt][nt][1]),
                          "+f"(acc[mt][nt][2]), "+f"(acc[mt][nt][3])
                        : "r"(af[mt][0]), "r"(af[mt][1]), "r"(af[mt][2]), "r"(af[mt][3]),
                          "r"(bfr[np][0 + s]), "r"(bfr[np][2 + s]));
                }
        }
        __syncthreads();
    }

    float* C = &g_logits[p][0][0];
#pragma unroll
    for (int mt = 0; mt < 2; mt++)
#pragma unroll
        for (int nt = 0; nt < 4; nt++) {
            int row = brow + wr * 32 + mt * 16 + (lane >> 2);
            int col = bcol + wc * 32 + nt * 8 + (lane & 3) * 2;
            *(float2*)(C + (size_t)row * P_ + col)       = make_float2(acc[mt][nt][0], acc[mt][nt][1]);
            *(float2*)(C + (size_t)(row + 8) * P_ + col) = make_float2(acc[mt][nt][2], acc[mt][nt][3]);
        }
}

// ---------------- kernel 3a: per-row log-sum-exp (1/TAU = 2) ---------------
__global__ void __launch_bounds__(128) k3_row() {
    int i = blockIdx.x, p = blockIdx.y;
    const float* row = &g_logits[p][i][0];
    int t = threadIdx.x;

    float v0 = row[t] * 2.f, v1 = row[t + 128] * 2.f;
    float v2 = row[t + 256] * 2.f, v3 = row[t + 384] * 2.f;

    __shared__ float wred[4];
    __shared__ float bc;

    float mx = fmaxf(fmaxf(v0, v1), fmaxf(v2, v3));
    mx = warpMax(mx);
    if ((t & 31) == 0) wred[t >> 5] = mx;
    __syncthreads();
    if (t < 32) {
        float m2 = (t < 4) ? wred[t] : -3.0e38f;
        m2 = warpMax(m2);
        if (t == 0) bc = m2;
    }
    __syncthreads();
    float M = bc;

    float es = __expf(v0 - M) + __expf(v1 - M) + __expf(v2 - M) + __expf(v3 - M);
    es = warpSum(es);
    __syncthreads();
    if ((t & 31) == 0) wred[t >> 5] = es;
    __syncthreads();
    if (t == 0) {
        float S = wred[0] + wred[1] + wred[2] + wred[3];
        float lse = M + __logf(S);
        g_rowloss[p * P_ + i] = lse - row[i] * 2.f;
    }
}

// ---------------- kernel 3b: final scalar ----------------------------------
__global__ void k3_final(float* __restrict__ out) {
    int t = threadIdx.x;  // 512 threads
    float rl = g_rowloss[t] + g_rowloss[t + 512] + g_rowloss[t + 1024];
    float cn = g_cnorm[t]   + g_cnorm[t + 512]   + g_cnorm[t + 1024];
    __shared__ float w1[16], w2[16];
    rl = warpSum(rl);
    cn = warpSum(cn);
    if ((t & 31) == 0) { w1[t >> 5] = rl; w2[t >> 5] = cn; }
    __syncthreads();
    if (t == 0) {
        float R = 0.f, C = 0.f;
        for (int i = 0; i < 16; i++) { R += w1[i]; C += w2[i]; }
        // loss_intra = 6 - (2/N)*sum||s||;  loss_inter = mean row losses
        out[0] = 6.f - (2.f / (float)N_) * C + R / (float)P_;
    }
}

// ---------------- launch ----------------------------------------------------
extern "C" void kernel_launch(void* const* d_in, const int* in_sizes, int n_in,
                              void* d_out, int out_size) {
    const float* fv    = (const float*)d_in[0];
    const float* fa    = (const float*)d_in[1];
    const float* fr    = (const float*)d_in[2];
    const int*   label = (const int*)d_in[3];
    (void)in_sizes; (void)n_in; (void)out_size;

    k0_all<<<1, 1024>>>(label);
    k1_centers<<<dim3(P_, 3), 256>>>(fv, fa, fr);
    k2_gemm<<<dim3(8, 8, 3), 128>>>();
    k3_row<<<dim3(P_, 3), 128>>>();
    k3_final<<<1, P_>>>((float*)d_out);
}

// round 4
// speedup vs baseline: 1.6914x; 1.0517x over previous
#include <cuda_runtime.h>
#include <cuda_bf16.h>
#include <math.h>

#define N_   8192
#define D_   2048
#define P_   512
#define EPSF 1e-12f

// ---------------- scratch (device globals; no allocation allowed) ----------
__device__ int   g_count[P_];
__device__ int   g_offset[P_];
__device__ int   g_members[N_];
__device__ __nv_bfloat16 g_cbf[3][P_][D_];   // unit centers, bf16 (GEMM operands)
__device__ float g_cnorm[3 * P_];            // ||sum_c|| per (modality, class)
__device__ float g_logits[3][P_][P_];        // un-scaled dot products
__device__ float g_rowloss[3 * P_];

// ---------------- helpers --------------------------------------------------
__device__ __forceinline__ float warpSum(float v) {
#pragma unroll
    for (int o = 16; o; o >>= 1) v += __shfl_xor_sync(0xffffffffu, v, o);
    return v;
}
__device__ __forceinline__ float warpMax(float v) {
#pragma unroll
    for (int o = 16; o; o >>= 1) v = fmaxf(v, __shfl_xor_sync(0xffffffffu, v, o));
    return v;
}
__device__ __forceinline__ unsigned bfpack(float lo, float hi) {
    unsigned a = (unsigned)__bfloat16_as_ushort(__float2bfloat16_rn(lo));
    unsigned b = (unsigned)__bfloat16_as_ushort(__float2bfloat16_rn(hi));
    return a | (b << 16);
}
__device__ __forceinline__ float dot8(const float4& x, const float4& y) {
    return x.x * x.x + x.y * x.y + x.z * x.z + x.w * x.w
         + y.x * y.x + y.y * y.y + y.z * y.z + y.w * y.w;
}

// ---------------- kernel 0: member list build (single block) ----------------
__global__ void __launch_bounds__(1024) k0_all(const int* __restrict__ label) {
    __shared__ int cnt[P_], off[P_];
    int t = threadIdx.x;
    if (t < P_) cnt[t] = 0;
    __syncthreads();
    for (int i = t; i < N_; i += 1024) atomicAdd(&cnt[label[i]], 1);
    __syncthreads();
    if (t < P_) off[t] = cnt[t];
    __syncthreads();
    for (int d = 1; d < P_; d <<= 1) {
        int v = 0;
        if (t < P_ && t >= d) v = off[t - d];
        __syncthreads();
        if (t < P_) off[t] += v;
        __syncthreads();
    }
    if (t < P_) {
        int exc = off[t] - cnt[t];
        g_count[t]  = cnt[t];
        g_offset[t] = exc;
        cnt[t] = exc;  // reuse as write cursor
    }
    __syncthreads();
    for (int i = t; i < N_; i += 1024) {
        int c = label[i];
        int pos = atomicAdd(&cnt[c], 1);
        g_members[pos] = i;
    }
}

// ---------------- kernel 1: centers + intra (paired, pipelined) -------------
// grid (P_, 3), block 256. Thread t owns float4 granules t and t+256.
// Two rows per iteration: halves barriers, doubles in-flight gmem bytes.
__global__ void __launch_bounds__(256) k1_centers(const float* __restrict__ f0,
                                                  const float* __restrict__ f1,
                                                  const float* __restrict__ f2) {
    int c = blockIdx.x, m = blockIdx.y;
    const float* f = (m == 0) ? f0 : ((m == 1) ? f1 : f2);
    int off = g_offset[c];
    int K   = g_count[c];
    int t   = threadIdx.x, w = t >> 5, lane = t & 31;

    __shared__ float wred[2][2][8];   // [buf][row-of-pair][warp]

    float a0 = 0.f, a1 = 0.f, a2 = 0.f, a3 = 0.f;
    float a4 = 0.f, a5 = 0.f, a6 = 0.f, a7 = 0.f;

    int k = 0;
    // odd-count head: process one row with its own reduction
    if (K & 1) {
        int row = g_members[off];
        const float4* rp = (const float4*)(f + (size_t)row * D_);
        float4 x = __ldg(&rp[t]);
        float4 y = __ldg(&rp[t + 256]);
        float ss = warpSum(dot8(x, y));
        if (lane == 0) wred[0][0][w] = ss;
        __syncthreads();
        float tot = wred[0][0][0] + wred[0][0][1] + wred[0][0][2] + wred[0][0][3]
                  + wred[0][0][4] + wred[0][0][5] + wred[0][0][6] + wred[0][0][7];
        float inv = rsqrtf(fmaxf(tot, 1e-24f));
        a0 = x.x * inv; a1 = x.y * inv; a2 = x.z * inv; a3 = x.w * inv;
        a4 = y.x * inv; a5 = y.y * inv; a6 = y.z * inv; a7 = y.w * inv;
        __syncthreads();
        k = 1;
    }

    if (k < K) {
        // preload pair (k, k+1)
        int r0 = g_members[off + k], r1 = g_members[off + k + 1];
        const float4* p0 = (const float4*)(f + (size_t)r0 * D_);
        const float4* p1 = (const float4*)(f + (size_t)r1 * D_);
        float4 x0 = __ldg(&p0[t]), y0 = __ldg(&p0[t + 256]);
        float4 x1 = __ldg(&p1[t]), y1 = __ldg(&p1[t + 256]);
        int buf = 0;

        for (; k < K; k += 2) {
            float4 nx0, ny0, nx1, ny1;
            if (k + 2 < K) {  // prefetch next pair: full iteration of slack
                int n0 = g_members[off + k + 2], n1 = g_members[off + k + 3];
                const float4* q0 = (const float4*)(f + (size_t)n0 * D_);
                const float4* q1 = (const float4*)(f + (size_t)n1 * D_);
                nx0 = __ldg(&q0[t]); ny0 = __ldg(&q0[t + 256]);
                nx1 = __ldg(&q1[t]); ny1 = __ldg(&q1[t + 256]);
            }
            float ss0 = warpSum(dot8(x0, y0));
            float ss1 = warpSum(dot8(x1, y1));
            if (lane == 0) { wred[buf][0][w] = ss0; wred[buf][1][w] = ss1; }
            __syncthreads();  // one barrier per TWO rows
            float t0 = wred[buf][0][0] + wred[buf][0][1] + wred[buf][0][2] + wred[buf][0][3]
                     + wred[buf][0][4] + wred[buf][0][5] + wred[buf][0][6] + wred[buf][0][7];
            float t1 = wred[buf][1][0] + wred[buf][1][1] + wred[buf][1][2] + wred[buf][1][3]
                     + wred[buf][1][4] + wred[buf][1][5] + wred[buf][1][6] + wred[buf][1][7];
            float i0 = rsqrtf(fmaxf(t0, 1e-24f));
            float i1 = rsqrtf(fmaxf(t1, 1e-24f));
            a0 += x0.x * i0 + x1.x * i1; a1 += x0.y * i0 + x1.y * i1;
            a2 += x0.z * i0 + x1.z * i1; a3 += x0.w * i0 + x1.w * i1;
            a4 += y0.x * i0 + y1.x * i1; a5 += y0.y * i0 + y1.y * i1;
            a6 += y0.z * i0 + y1.z * i1; a7 += y0.w * i0 + y1.w * i1;
            x0 = nx0; y0 = ny0; x1 = nx1; y1 = ny1;
            buf ^= 1;
        }
    }

    float ss2 = a0 * a0 + a1 * a1 + a2 * a2 + a3 * a3
              + a4 * a4 + a5 * a5 + a6 * a6 + a7 * a7;
    ss2 = warpSum(ss2);
    __syncthreads();
    if (lane == 0) wred[0][0][w] = ss2;
    __syncthreads();
    float tot2 = wred[0][0][0] + wred[0][0][1] + wred[0][0][2] + wred[0][0][3]
               + wred[0][0][4] + wred[0][0][5] + wred[0][0][6] + wred[0][0][7];
    float nrm  = sqrtf(tot2);
    float inv2 = 1.f / fmaxf(nrm, EPSF);

    __nv_bfloat16* cb = &g_cbf[m][c][0];
    uint2 u0, u1;
    u0.x = bfpack(a0 * inv2, a1 * inv2); u0.y = bfpack(a2 * inv2, a3 * inv2);
    u1.x = bfpack(a4 * inv2, a5 * inv2); u1.y = bfpack(a6 * inv2, a7 * inv2);
    *(uint2*)(cb + 4 * t)         = u0;
    *(uint2*)(cb + 4 * (t + 256)) = u1;
    if (t == 0) g_cnorm[m * P_ + c] = nrm;
}

// ---------------- kernel 2: three 512x512xK=2048 bf16 mma GEMMs ------------
// grid (8, 8, 3), block 128 (4 warps, 2x2, each warp 32x32).
// smem tile: 64 rows x 64 bf16 (128 B/row); XOR swizzle on 16B granules:
//   byte(row, g) = row*128 + ((g ^ (row & 7)) << 4)
#define KC_ 64
__device__ __forceinline__ unsigned sw_off(int row, int g) {
    return (unsigned)(row * 128 + ((g ^ (row & 7)) << 4));
}

__global__ void __launch_bounds__(128) k2_gemm() {
    int p  = blockIdx.z;
    int pa = (p == 2) ? 1 : 0;
    int pb = (p == 0) ? 1 : 2;
    const __nv_bfloat16* A = &g_cbf[pa][0][0];
    const __nv_bfloat16* B = &g_cbf[pb][0][0];

    __shared__ __align__(16) unsigned char As[64 * 128];
    __shared__ __align__(16) unsigned char Bs[64 * 128];
    unsigned asb = (unsigned)__cvta_generic_to_shared(As);
    unsigned bsb = (unsigned)__cvta_generic_to_shared(Bs);

    int t = threadIdx.x, lane = t & 31, warp = t >> 5;
    int wr = warp >> 1, wc = warp & 1;
    int brow = blockIdx.y * 64, bcol = blockIdx.x * 64;

    float acc[2][4][4];
#pragma unroll
    for (int mt = 0; mt < 2; mt++)
#pragma unroll
        for (int nt = 0; nt < 4; nt++)
#pragma unroll
            for (int e = 0; e < 4; e++) acc[mt][nt][e] = 0.f;

    int rsel = lane & 15, gsel = lane >> 4;

    uint4 ga[4], gb[4];
#pragma unroll
    for (int j = 0; j < 4; j++) {
        int i = t + j * 128, row = i >> 3, g = i & 7;
        ga[j] = *(const uint4*)(A + (size_t)(brow + row) * D_ + g * 8);
        gb[j] = *(const uint4*)(B + (size_t)(bcol + row) * D_ + g * 8);
    }

    for (int kc = 0; kc < D_ / KC_; kc++) {
#pragma unroll
        for (int j = 0; j < 4; j++) {
            int i = t + j * 128, row = i >> 3, g = i & 7;
            *(uint4*)(As + sw_off(row, g)) = ga[j];
            *(uint4*)(Bs + sw_off(row, g)) = gb[j];
        }
        __syncthreads();

        if (kc + 1 < D_ / KC_) {
            int co = (kc + 1) * KC_;
#pragma unroll
            for (int j = 0; j < 4; j++) {
                int i = t + j * 128, row = i >> 3, g = i & 7;
                ga[j] = *(const uint4*)(A + (size_t)(brow + row) * D_ + co + g * 8);
                gb[j] = *(const uint4*)(B + (size_t)(bcol + row) * D_ + co + g * 8);
            }
        }

#pragma unroll
        for (int kh = 0; kh < 4; kh++) {
            unsigned af[2][4], bfr[2][4];
#pragma unroll
            for (int mt = 0; mt < 2; mt++) {
                unsigned ad = asb + sw_off(wr * 32 + mt * 16 + rsel, kh * 2 + gsel);
                asm volatile("ldmatrix.sync.aligned.m8n8.x4.shared.b16 {%0,%1,%2,%3}, [%4];"
                             : "=r"(af[mt][0]), "=r"(af[mt][1]), "=r"(af[mt][2]), "=r"(af[mt][3])
                             : "r"(ad));
            }
#pragma unroll
            for (int np = 0; np < 2; np++) {
                unsigned bd = bsb + sw_off(wc * 32 + np * 16 + rsel, kh * 2 + gsel);
                asm volatile("ldmatrix.sync.aligned.m8n8.x4.shared.b16 {%0,%1,%2,%3}, [%4];"
                             : "=r"(bfr[np][0]), "=r"(bfr[np][1]), "=r"(bfr[np][2]), "=r"(bfr[np][3])
                             : "r"(bd));
            }
#pragma unroll
            for (int mt = 0; mt < 2; mt++)
#pragma unroll
                for (int nt = 0; nt < 4; nt++) {
                    int np = nt >> 1, s = nt & 1;
                    asm volatile(
                        "mma.sync.aligned.m16n8k16.row.col.f32.bf16.bf16.f32 "
                        "{%0,%1,%2,%3},{%4,%5,%6,%7},{%8,%9},{%0,%1,%2,%3};"
                        : "+f"(acc[mt][nt][0]), "+f"(acc[mt][nt][1]),
                          "+f"(acc[mt][nt][2]), "+f"(acc[mt][nt][3])
                        : "r"(af[mt][0]), "r"(af[mt][1]), "r"(af[mt][2]), "r"(af[mt][3]),
                          "r"(bfr[np][0 + s]), "r"(bfr[np][2 + s]));
                }
        }
        __syncthreads();
    }

    float* C = &g_logits[p][0][0];
#pragma unroll
    for (int mt = 0; mt < 2; mt++)
#pragma unroll
        for (int nt = 0; nt < 4; nt++) {
            int row = brow + wr * 32 + mt * 16 + (lane >> 2);
            int col = bcol + wc * 32 + nt * 8 + (lane & 3) * 2;
            *(float2*)(C + (size_t)row * P_ + col)       = make_float2(acc[mt][nt][0], acc[mt][nt][1]);
            *(float2*)(C + (size_t)(row + 8) * P_ + col) = make_float2(acc[mt][nt][2], acc[mt][nt][3]);
        }
}

// ---------------- kernel 3a: per-row log-sum-exp, warp-per-row -------------
// grid 192, block 256 (8 warps). No barriers, all-shfl reductions. 1/TAU = 2.
__global__ void __launch_bounds__(256) k3_row() {
    int warp = threadIdx.x >> 5, lane = threadIdx.x & 31;
    int gid = blockIdx.x * 8 + warp;          // 0 .. 1535
    int p = gid >> 9, i = gid & (P_ - 1);
    const float* row = &g_logits[p][i][0];

    float4 v[4];
#pragma unroll
    for (int j = 0; j < 4; j++) {
        float4 u = *(const float4*)(row + lane * 4 + j * 128);
        v[j] = make_float4(u.x * 2.f, u.y * 2.f, u.z * 2.f, u.w * 2.f);
    }
    float mx = -3.0e38f;
#pragma unroll
    for (int j = 0; j < 4; j++)
        mx = fmaxf(mx, fmaxf(fmaxf(v[j].x, v[j].y), fmaxf(v[j].z, v[j].w)));
    mx = warpMax(mx);

    float es = 0.f;
#pragma unroll
    for (int j = 0; j < 4; j++)
        es += __expf(v[j].x - mx) + __expf(v[j].y - mx)
            + __expf(v[j].z - mx) + __expf(v[j].w - mx);
    es = warpSum(es);

    if (lane == 0) {
        float lse = mx + __logf(es);
        g_rowloss[p * P_ + i] = lse - row[i] * 2.f;
    }
}

// ---------------- kernel 3b: final scalar ----------------------------------
__global__ void k3_final(float* __restrict__ out) {
    int t = threadIdx.x;  // 512 threads
    float rl = g_rowloss[t] + g_rowloss[t + 512] + g_rowloss[t + 1024];
    float cn = g_cnorm[t]   + g_cnorm[t + 512]   + g_cnorm[t + 1024];
    __shared__ float w1[16], w2[16];
    rl = warpSum(rl);
    cn = warpSum(cn);
    if ((t & 31) == 0) { w1[t >> 5] = rl; w2[t >> 5] = cn; }
    __syncthreads();
    if (t == 0) {
        float R = 0.f, C = 0.f;
        for (int i = 0; i < 16; i++) { R += w1[i]; C += w2[i]; }
        // loss_intra = 6 - (2/N)*sum||s||;  loss_inter = mean row losses
        out[0] = 6.f - (2.f / (float)N_) * C + R / (float)P_;
    }
}

// ---------------- launch ----------------------------------------------------
extern "C" void kernel_launch(void* const* d_in, const int* in_sizes, int n_in,
                              void* d_out, int out_size) {
    const float* fv    = (const float*)d_in[0];
    const float* fa    = (const float*)d_in[1];
    const float* fr    = (const float*)d_in[2];
    const int*   label = (const int*)d_in[3];
    (void)in_sizes; (void)n_in; (void)out_size;

    k0_all<<<1, 1024>>>(label);
    k1_centers<<<dim3(P_, 3), 256>>>(fv, fa, fr);
    k2_gemm<<<dim3(8, 8, 3), 128>>>();
    k3_row<<<192, 256>>>();
    k3_final<<<1, P_>>>((float*)d_out);
}

// round 5
// speedup vs baseline: 1.7594x; 1.0402x over previous
#include <cuda_runtime.h>
#include <cuda_bf16.h>
#include <math.h>

#define N_   8192
#define D_   2048
#define P_   512
#define EPSF 1e-12f
#define S_   4          // cp.async ring depth in k1

// ---------------- scratch (device globals; no allocation allowed) ----------
__device__ int   g_count[P_];
__device__ int   g_offset[P_];
__device__ int   g_members[N_];
__device__ __nv_bfloat16 g_cbf[3][P_][D_];   // unit centers, bf16 (GEMM operands)
__device__ float g_cnorm[3 * P_];            // ||sum_c|| per (modality, class)
__device__ float g_logits[3][P_][P_];        // un-scaled dot products
__device__ float g_rowloss[3 * P_];

// ---------------- helpers --------------------------------------------------
__device__ __forceinline__ float warpSum(float v) {
#pragma unroll
    for (int o = 16; o; o >>= 1) v += __shfl_xor_sync(0xffffffffu, v, o);
    return v;
}
__device__ __forceinline__ float warpMax(float v) {
#pragma unroll
    for (int o = 16; o; o >>= 1) v = fmaxf(v, __shfl_xor_sync(0xffffffffu, v, o));
    return v;
}
__device__ __forceinline__ unsigned bfpack(float lo, float hi) {
    unsigned a = (unsigned)__bfloat16_as_ushort(__float2bfloat16_rn(lo));
    unsigned b = (unsigned)__bfloat16_as_ushort(__float2bfloat16_rn(hi));
    return a | (b << 16);
}
__device__ __forceinline__ void cpa16(void* dst, const void* src) {
    unsigned d = (unsigned)__cvta_generic_to_shared(dst);
    asm volatile("cp.async.cg.shared.global [%0], [%1], 16;\n" :: "r"(d), "l"(src));
}
__device__ __forceinline__ void cpa_commit() {
    asm volatile("cp.async.commit_group;\n" ::: "memory");
}
template <int Npend>
__device__ __forceinline__ void cpa_wait() {
    asm volatile("cp.async.wait_group %0;\n" :: "n"(Npend) : "memory");
}

// ---------------- kernel 0: member list build (single block) ----------------
__global__ void __launch_bounds__(1024) k0_all(const int* __restrict__ label) {
    __shared__ int cnt[P_];
    __shared__ int wsum[16];
    int t = threadIdx.x, lane = t & 31, w = t >> 5;

    int lv[8];
#pragma unroll
    for (int j = 0; j < 8; j++) lv[j] = __ldg(&label[t + j * 1024]);  // 8 loads in flight

    if (t < P_) cnt[t] = 0;
    __syncthreads();
#pragma unroll
    for (int j = 0; j < 8; j++) atomicAdd(&cnt[lv[j]], 1);
    __syncthreads();

    // shfl-based exclusive scan of cnt[0..511] using first 16 warps
    int myc = 0, inc = 0;
    if (t < P_) {
        myc = cnt[t];
        inc = myc;
#pragma unroll
        for (int o = 1; o < 32; o <<= 1) {
            int v = __shfl_up_sync(0xffffffffu, inc, o);
            if (lane >= o) inc += v;
        }
        if (lane == 31) wsum[w] = inc;
    }
    __syncthreads();
    if (t < 32) {  // scan the 16 warp sums
        int v = (t < 16) ? wsum[t] : 0;
        int s = v;
#pragma unroll
        for (int o = 1; o < 32; o <<= 1) {
            int u = __shfl_up_sync(0xffffffffu, s, o);
            if (lane >= o) s += u;
        }
        if (t < 16) wsum[t] = s - v;  // exclusive warp offsets
    }
    __syncthreads();
    if (t < P_) {
        int exc = wsum[w] + inc - myc;  // exclusive prefix
        g_count[t]  = myc;
        g_offset[t] = exc;
        cnt[t] = exc;  // reuse as cursor
    }
    __syncthreads();
#pragma unroll
    for (int j = 0; j < 8; j++) {
        int c = lv[j];
        int pos = atomicAdd(&cnt[c], 1);
        g_members[pos] = t + j * 1024;
    }
}

// ---------------- kernel 1: centers via cp.async smem ring ------------------
// grid (P_, 3), block 256. 4-stage ring of full rows (8 KB each, 32 KB smem).
// Async engine holds 4 rows in flight with no register cost -> high occupancy,
// DRAM-throughput-bound.
__global__ void __launch_bounds__(256) k1_centers(const float* __restrict__ f0,
                                                  const float* __restrict__ f1,
                                                  const float* __restrict__ f2) {
    int c = blockIdx.x, m = blockIdx.y;
    const float* f = (m == 0) ? f0 : ((m == 1) ? f1 : f2);
    int off = g_offset[c];
    int K   = g_count[c];
    int t   = threadIdx.x, w = t >> 5, lane = t & 31;

    __shared__ __align__(16) float stg[S_][D_];   // 32 KB ring
    __shared__ float wred[8];

    // prologue: fill the ring
#pragma unroll
    for (int s = 0; s < S_; s++) {
        if (s < K) {
            int row = __ldg(&g_members[off + s]);
            const float* src = f + (size_t)row * D_;
            cpa16(&stg[s][t * 4], src + t * 4);
            cpa16(&stg[s][1024 + t * 4], src + 1024 + t * 4);
        }
        cpa_commit();
    }

    float a0 = 0.f, a1 = 0.f, a2 = 0.f, a3 = 0.f;
    float a4 = 0.f, a5 = 0.f, a6 = 0.f, a7 = 0.f;

    for (int k = 0; k < K; k++) {
        cpa_wait<S_ - 1>();     // stage k's data has landed
        __syncthreads();
        int sb = k & (S_ - 1);
        float4 x = *(const float4*)&stg[sb][t * 4];
        float4 y = *(const float4*)&stg[sb][1024 + t * 4];
        float ss = x.x * x.x + x.y * x.y + x.z * x.z + x.w * x.w
                 + y.x * y.x + y.y * y.y + y.z * y.z + y.w * y.w;
        ss = warpSum(ss);
        if (lane == 0) wred[w] = ss;
        __syncthreads();        // also guarantees all LDS of stage sb are done
        float tot = wred[0] + wred[1] + wred[2] + wred[3]
                  + wred[4] + wred[5] + wred[6] + wred[7];
        float inv = rsqrtf(fmaxf(tot, 1e-24f));
        a0 += x.x * inv; a1 += x.y * inv; a2 += x.z * inv; a3 += x.w * inv;
        a4 += y.x * inv; a5 += y.y * inv; a6 += y.z * inv; a7 += y.w * inv;

        int kn = k + S_;        // refill the just-freed stage
        if (kn < K) {
            int row = __ldg(&g_members[off + kn]);
            const float* src = f + (size_t)row * D_;
            cpa16(&stg[sb][t * 4], src + t * 4);
            cpa16(&stg[sb][1024 + t * 4], src + 1024 + t * 4);
        }
        cpa_commit();
    }

    float ss2 = a0 * a0 + a1 * a1 + a2 * a2 + a3 * a3
              + a4 * a4 + a5 * a5 + a6 * a6 + a7 * a7;
    ss2 = warpSum(ss2);
    __syncthreads();            // wred reuse safe
    if (lane == 0) wred[w] = ss2;
    __syncthreads();
    float tot2 = wred[0] + wred[1] + wred[2] + wred[3]
               + wred[4] + wred[5] + wred[6] + wred[7];
    float nrm  = sqrtf(tot2);
    float inv2 = 1.f / fmaxf(nrm, EPSF);

    __nv_bfloat16* cb = &g_cbf[m][c][0];
    uint2 u0, u1;
    u0.x = bfpack(a0 * inv2, a1 * inv2); u0.y = bfpack(a2 * inv2, a3 * inv2);
    u1.x = bfpack(a4 * inv2, a5 * inv2); u1.y = bfpack(a6 * inv2, a7 * inv2);
    *(uint2*)(cb + 4 * t)         = u0;
    *(uint2*)(cb + 4 * (t + 256)) = u1;
    if (t == 0) g_cnorm[m * P_ + c] = nrm;
}

// ---------------- kernel 2: three 512x512xK=2048 bf16 mma GEMMs ------------
// grid (8, 8, 3), block 128 (4 warps, 2x2, each warp 32x32).
// smem tile: 64 rows x 64 bf16 (128 B/row); XOR swizzle on 16B granules.
#define KC_ 64
__device__ __forceinline__ unsigned sw_off(int row, int g) {
    return (unsigned)(row * 128 + ((g ^ (row & 7)) << 4));
}

__global__ void __launch_bounds__(128) k2_gemm() {
    int p  = blockIdx.z;
    int pa = (p == 2) ? 1 : 0;
    int pb = (p == 0) ? 1 : 2;
    const __nv_bfloat16* A = &g_cbf[pa][0][0];
    const __nv_bfloat16* B = &g_cbf[pb][0][0];

    __shared__ __align__(16) unsigned char As[64 * 128];
    __shared__ __align__(16) unsigned char Bs[64 * 128];
    unsigned asb = (unsigned)__cvta_generic_to_shared(As);
    unsigned bsb = (unsigned)__cvta_generic_to_shared(Bs);

    int t = threadIdx.x, lane = t & 31, warp = t >> 5;
    int wr = warp >> 1, wc = warp & 1;
    int brow = blockIdx.y * 64, bcol = blockIdx.x * 64;

    float acc[2][4][4];
#pragma unroll
    for (int mt = 0; mt < 2; mt++)
#pragma unroll
        for (int nt = 0; nt < 4; nt++)
#pragma unroll
            for (int e = 0; e < 4; e++) acc[mt][nt][e] = 0.f;

    int rsel = lane & 15, gsel = lane >> 4;

    uint4 ga[4], gb[4];
#pragma unroll
    for (int j = 0; j < 4; j++) {
        int i = t + j * 128, row = i >> 3, g = i & 7;
        ga[j] = *(const uint4*)(A + (size_t)(brow + row) * D_ + g * 8);
        gb[j] = *(const uint4*)(B + (size_t)(bcol + row) * D_ + g * 8);
    }

    for (int kc = 0; kc < D_ / KC_; kc++) {
#pragma unroll
        for (int j = 0; j < 4; j++) {
            int i = t + j * 128, row = i >> 3, g = i & 7;
            *(uint4*)(As + sw_off(row, g)) = ga[j];
            *(uint4*)(Bs + sw_off(row, g)) = gb[j];
        }
        __syncthreads();

        if (kc + 1 < D_ / KC_) {
            int co = (kc + 1) * KC_;
#pragma unroll
            for (int j = 0; j < 4; j++) {
                int i = t + j * 128, row = i >> 3, g = i & 7;
                ga[j] = *(const uint4*)(A + (size_t)(brow + row) * D_ + co + g * 8);
                gb[j] = *(const uint4*)(B + (size_t)(bcol + row) * D_ + co + g * 8);
            }
        }

#pragma unroll
        for (int kh = 0; kh < 4; kh++) {
            unsigned af[2][4], bfr[2][4];
#pragma unroll
            for (int mt = 0; mt < 2; mt++) {
                unsigned ad = asb + sw_off(wr * 32 + mt * 16 + rsel, kh * 2 + gsel);
                asm volatile("ldmatrix.sync.aligned.m8n8.x4.shared.b16 {%0,%1,%2,%3}, [%4];"
                             : "=r"(af[mt][0]), "=r"(af[mt][1]), "=r"(af[mt][2]), "=r"(af[mt][3])
                             : "r"(ad));
            }
#pragma unroll
            for (int np = 0; np < 2; np++) {
                unsigned bd = bsb + sw_off(wc * 32 + np * 16 + rsel, kh * 2 + gsel);
                asm volatile("ldmatrix.sync.aligned.m8n8.x4.shared.b16 {%0,%1,%2,%3}, [%4];"
                             : "=r"(bfr[np][0]), "=r"(bfr[np][1]), "=r"(bfr[np][2]), "=r"(bfr[np][3])
                             : "r"(bd));
            }
#pragma unroll
            for (int mt = 0; mt < 2; mt++)
#pragma unroll
                for (int nt = 0; nt < 4; nt++) {
                    int np = nt >> 1, s = nt & 1;
                    asm volatile(
                        "mma.sync.aligned.m16n8k16.row.col.f32.bf16.bf16.f32 "
                        "{%0,%1,%2,%3},{%4,%5,%6,%7},{%8,%9},{%0,%1,%2,%3};"
                        : "+f"(acc[mt][nt][0]), "+f"(acc[mt][nt][1]),
                          "+f"(acc[mt][nt][2]), "+f"(acc[mt][nt][3])
                        : "r"(af[mt][0]), "r"(af[mt][1]), "r"(af[mt][2]), "r"(af[mt][3]),
                          "r"(bfr[np][0 + s]), "r"(bfr[np][2 + s]));
                }
        }
        __syncthreads();
    }

    float* C = &g_logits[p][0][0];
#pragma unroll
    for (int mt = 0; mt < 2; mt++)
#pragma unroll
        for (int nt = 0; nt < 4; nt++) {
            int row = brow + wr * 32 + mt * 16 + (lane >> 2);
            int col = bcol + wc * 32 + nt * 8 + (lane & 3) * 2;
            *(float2*)(C + (size_t)row * P_ + col)       = make_float2(acc[mt][nt][0], acc[mt][nt][1]);
            *(float2*)(C + (size_t)(row + 8) * P_ + col) = make_float2(acc[mt][nt][2], acc[mt][nt][3]);
        }
}

// ---------------- kernel 3a: per-row log-sum-exp, warp-per-row -------------
// grid 384, block 128 (4 warps). No barriers, all-shfl. 1/TAU = 2.
__global__ void __launch_bounds__(128) k3_row() {
    int warp = threadIdx.x >> 5, lane = threadIdx.x & 31;
    int gid = blockIdx.x * 4 + warp;          // 0 .. 1535
    int p = gid >> 9, i = gid & (P_ - 1);
    const float* row = &g_logits[p][i][0];

    float4 v[4];
#pragma unroll
    for (int j = 0; j < 4; j++) {
        float4 u = *(const float4*)(row + lane * 4 + j * 128);
        v[j] = make_float4(u.x * 2.f, u.y * 2.f, u.z * 2.f, u.w * 2.f);
    }
    float mx = -3.0e38f;
#pragma unroll
    for (int j = 0; j < 4; j++)
        mx = fmaxf(mx, fmaxf(fmaxf(v[j].x, v[j].y), fmaxf(v[j].z, v[j].w)));
    mx = warpMax(mx);

    float es = 0.f;
#pragma unroll
    for (int j = 0; j < 4; j++)
        es += __expf(v[j].x - mx) + __expf(v[j].y - mx)
            + __expf(v[j].z - mx) + __expf(v[j].w - mx);
    es = warpSum(es);

    if (lane == 0) {
        float lse = mx + __logf(es);
        g_rowloss[p * P_ + i] = lse - row[i] * 2.f;
    }
}

// ---------------- kernel 3b: final scalar ----------------------------------
__global__ void k3_final(float* __restrict__ out) {
    int t = threadIdx.x;  // 512 threads
    float rl = g_rowloss[t] + g_rowloss[t + 512] + g_rowloss[t + 1024];
    float cn = g_cnorm[t]   + g_cnorm[t + 512]   + g_cnorm[t + 1024];
    __shared__ float w1[16], w2[16];
    rl = warpSum(rl);
    cn = warpSum(cn);
    if ((t & 31) == 0) { w1[t >> 5] = rl; w2[t >> 5] = cn; }
    __syncthreads();
    if (t == 0) {
        float R = 0.f, C = 0.f;
        for (int i = 0; i < 16; i++) { R += w1[i]; C += w2[i]; }
        // loss_intra = 6 - (2/N)*sum||s||;  loss_inter = mean row losses
        out[0] = 6.f - (2.f / (float)N_) * C + R / (float)P_;
    }
}

// ---------------- launch ----------------------------------------------------
extern "C" void kernel_launch(void* const* d_in, const int* in_sizes, int n_in,
                              void* d_out, int out_size) {
    const float* fv    = (const float*)d_in[0];
    const float* fa    = (const float*)d_in[1];
    const float* fr    = (const float*)d_in[2];
    const int*   label = (const int*)d_in[3];
    (void)in_sizes; (void)n_in; (void)out_size;

    k0_all<<<1, 1024>>>(label);
    k1_centers<<<dim3(P_, 3), 256>>>(fv, fa, fr);
    k2_gemm<<<dim3(8, 8, 3), 128>>>();
    k3_row<<<384, 128>>>();
    k3_final<<<1, P_>>>((float*)d_out);
}

// round 7
// speedup vs baseline: 1.9258x; 1.0946x over previous
#include <cuda_runtime.h>
#include <cuda_bf16.h>
#include <math.h>

#define N_   8192
#define D_   2048
#define P_   512
#define NB_  16          // k0 partition blocks (512 samples each)
#define EPSF 1e-12f
#define S_   4           // cp.async ring depth in k1

// ---------------- scratch (device globals; no allocation allowed) ----------
__device__ int   g_count[P_];
__device__ int   g_offset[P_];
__device__ int   g_members[N_];
__device__ int   g_pc[NB_][P_];       // per-partition class histograms
__device__ int   g_base[NB_][P_];     // per-partition write bases
__device__ __nv_bfloat16 g_cbf[3][P_][D_];   // unit centers, bf16
__device__ float g_expsum[3][P_];     // per-row sum of exp(2*dot)
__device__ float g_sumnorm;           // sum ||s_c|| over all (m, c)
__device__ float g_sumdiag;           // sum of diagonal dots over all (p, i)

// ---------------- helpers --------------------------------------------------
__device__ __forceinline__ float warpSum(float v) {
#pragma unroll
    for (int o = 16; o; o >>= 1) v += __shfl_xor_sync(0xffffffffu, v, o);
    return v;
}
__device__ __forceinline__ unsigned bfpack(float lo, float hi) {
    unsigned a = (unsigned)__bfloat16_as_ushort(__float2bfloat16_rn(lo));
    unsigned b = (unsigned)__bfloat16_as_ushort(__float2bfloat16_rn(hi));
    return a | (b << 16);
}
__device__ __forceinline__ float dot8(const float4& x, const float4& y) {
    return x.x * x.x + x.y * x.y + x.z * x.z + x.w * x.w
         + y.x * y.x + y.y * y.y + y.z * y.z + y.w * y.w;
}
__device__ __forceinline__ void cpa16(void* dst, const void* src) {
    unsigned d = (unsigned)__cvta_generic_to_shared(dst);
    asm volatile("cp.async.cg.shared.global [%0], [%1], 16;\n" :: "r"(d), "l"(src));
}
__device__ __forceinline__ void cpa_commit() {
    asm volatile("cp.async.commit_group;\n" ::: "memory");
}
template <int Npend>
__device__ __forceinline__ void cpa_wait() {
    asm volatile("cp.async.wait_group %0;\n" :: "n"(Npend) : "memory");
}

// ---------------- kernel 0a: per-partition histogram (grid NB_, 512) -------
__global__ void __launch_bounds__(512) k0a_hist(const int* __restrict__ label) {
    __shared__ int h[P_];
    int t = threadIdx.x, b = blockIdx.x;
    h[t] = 0;
    __syncthreads();
    int l = __ldg(&label[b * 512 + t]);
    atomicAdd(&h[l], 1);
    __syncthreads();
    g_pc[b][t] = h[t];
}

// ---------------- kernel 0b: scan + bases + zero accumulators (1 block) ----
__global__ void __launch_bounds__(512) k0b_scan() {
    int t = threadIdx.x, lane = t & 31, w = t >> 5;
    int pc[NB_];
    int tot = 0;
#pragma unroll
    for (int b = 0; b < NB_; b++) { pc[b] = g_pc[b][t]; tot += pc[b]; }

    int inc = tot;
#pragma unroll
    for (int o = 1; o < 32; o <<= 1) {
        int v = __shfl_up_sync(0xffffffffu, inc, o);
        if (lane >= o) inc += v;
    }
    __shared__ int ws[16];
    if (lane == 31) ws[w] = inc;
    __syncthreads();
    if (t < 32) {
        int v = (t < 16) ? ws[t] : 0;
        int s = v;
#pragma unroll
        for (int o = 1; o < 32; o <<= 1) {
            int u = __shfl_up_sync(0xffffffffu, s, o);
            if (lane >= o) s += u;
        }
        if (t < 16) ws[t] = s - v;   // exclusive warp offsets
    }
    __syncthreads();
    int exc = ws[w] + inc - tot;     // exclusive class prefix
    g_count[t]  = tot;
    g_offset[t] = exc;
    int run = exc;
#pragma unroll
    for (int b = 0; b < NB_; b++) { g_base[b][t] = run; run += pc[b]; }

    // zero the accumulators used downstream
    g_expsum[0][t] = 0.f; g_expsum[1][t] = 0.f; g_expsum[2][t] = 0.f;
    if (t == 0) { g_sumnorm = 0.f; g_sumdiag = 0.f; }
}

// ---------------- kernel 0c: parallel fill (grid NB_, 512) -----------------
__global__ void __launch_bounds__(512) k0c_fill(const int* __restrict__ label) {
    __shared__ int cur[P_];
    int t = threadIdx.x, b = blockIdx.x;
    cur[t] = g_base[b][t];
    __syncthreads();
    int i = b * 512 + t;
    int c = __ldg(&label[i]);
    int pos = atomicAdd(&cur[c], 1);
    g_members[pos] = i;
}

// ---------------- kernel 1: centers via cp.async smem ring ------------------
// grid (P_, 3), block 256. 4-stage ring of full rows (8 KB each, 32 KB smem).
// One barrier per row; each thread only touches its own 32 B of each stage.
__global__ void __launch_bounds__(256) k1_centers(const float* __restrict__ f0,
                                                  const float* __restrict__ f1,
                                                  const float* __restrict__ f2) {
    int c = blockIdx.x, m = blockIdx.y;
    const float* f = (m == 0) ? f0 : ((m == 1) ? f1 : f2);
    int off = g_offset[c];
    int K   = g_count[c];
    int t   = threadIdx.x, w = t >> 5, lane = t & 31;

    __shared__ __align__(16) float stg[S_][D_];   // 32 KB ring
    __shared__ float wred[2][8];

#pragma unroll
    for (int s = 0; s < S_; s++) {
        if (s < K) {
            int row = __ldg(&g_members[off + s]);
            const float* src = f + (size_t)row * D_;
            cpa16(&stg[s][t * 4], src + t * 4);
            cpa16(&stg[s][1024 + t * 4], src + 1024 + t * 4);
        }
        cpa_commit();
    }

    float a0 = 0.f, a1 = 0.f, a2 = 0.f, a3 = 0.f;
    float a4 = 0.f, a5 = 0.f, a6 = 0.f, a7 = 0.f;

    for (int k = 0; k < K; k++) {
        cpa_wait<S_ - 1>();          // this thread's stage-k copy landed
        int sb = k & (S_ - 1);
        float4 x = *(const float4*)&stg[sb][t * 4];
        float4 y = *(const float4*)&stg[sb][1024 + t * 4];
        int kn = k + S_;             // refill own region (no cross-thread hazard)
        if (kn < K) {
            int row = __ldg(&g_members[off + kn]);
            const float* src = f + (size_t)row * D_;
            cpa16(&stg[sb][t * 4], src + t * 4);
            cpa16(&stg[sb][1024 + t * 4], src + 1024 + t * 4);
        }
        cpa_commit();
        float ss = warpSum(dot8(x, y));
        if (lane == 0) wred[k & 1][w] = ss;
        __syncthreads();             // single barrier per row
        float tot = wred[k & 1][0] + wred[k & 1][1] + wred[k & 1][2] + wred[k & 1][3]
                  + wred[k & 1][4] + wred[k & 1][5] + wred[k & 1][6] + wred[k & 1][7];
        float inv = rsqrtf(fmaxf(tot, 1e-24f));
        a0 += x.x * inv; a1 += x.y * inv; a2 += x.z * inv; a3 += x.w * inv;
        a4 += y.x * inv; a5 += y.y * inv; a6 += y.z * inv; a7 += y.w * inv;
    }

    float ss2 = a0 * a0 + a1 * a1 + a2 * a2 + a3 * a3
              + a4 * a4 + a5 * a5 + a6 * a6 + a7 * a7;
    ss2 = warpSum(ss2);
    __syncthreads();
    if (lane == 0) wred[0][w] = ss2;
    __syncthreads();
    float tot2 = wred[0][0] + wred[0][1] + wred[0][2] + wred[0][3]
               + wred[0][4] + wred[0][5] + wred[0][6] + wred[0][7];
    float nrm  = sqrtf(tot2);
    float inv2 = 1.f / fmaxf(nrm, EPSF);

    __nv_bfloat16* cb = &g_cbf[m][c][0];
    uint2 u0, u1;
    u0.x = bfpack(a0 * inv2, a1 * inv2); u0.y = bfpack(a2 * inv2, a3 * inv2);
    u1.x = bfpack(a4 * inv2, a5 * inv2); u1.y = bfpack(a6 * inv2, a7 * inv2);
    *(uint2*)(cb + 4 * t)         = u0;
    *(uint2*)(cb + 4 * (t + 256)) = u1;
    if (t == 0) atomicAdd(&g_sumnorm, nrm);
}

// ---------------- kernel 2: bf16 mma GEMMs + fused exp-sum epilogue --------
// grid (8, 8, 3), block 128 (4 warps, 2x2, each warp 32x32).
// Logits are bounded (|dot|<=1 -> |2*dot|<=2), so sum-exp needs no max shift
// and decomposes per tile: epilogue exps accumulators and atomicAdds row sums.
#define KC_ 64
__device__ __forceinline__ unsigned sw_off(int row, int g) {
    return (unsigned)(row * 128 + ((g ^ (row & 7)) << 4));
}

__global__ void __launch_bounds__(128) k2_gemm() {
    int p  = blockIdx.z;
    int pa = (p == 2) ? 1 : 0;
    int pb = (p == 0) ? 1 : 2;
    const __nv_bfloat16* A = &g_cbf[pa][0][0];
    const __nv_bfloat16* B = &g_cbf[pb][0][0];

    __shared__ __align__(16) unsigned char As[64 * 128];
    __shared__ __align__(16) unsigned char Bs[64 * 128];
    unsigned asb = (unsigned)__cvta_generic_to_shared(As);
    unsigned bsb = (unsigned)__cvta_generic_to_shared(Bs);

    int t = threadIdx.x, lane = t & 31, warp = t >> 5;
    int wr = warp >> 1, wc = warp & 1;
    int brow = blockIdx.y * 64, bcol = blockIdx.x * 64;

    float acc[2][4][4];
#pragma unroll
    for (int mt = 0; mt < 2; mt++)
#pragma unroll
        for (int nt = 0; nt < 4; nt++)
#pragma unroll
            for (int e = 0; e < 4; e++) acc[mt][nt][e] = 0.f;

    int rsel = lane & 15, gsel = lane >> 4;

    uint4 ga[4], gb[4];
#pragma unroll
    for (int j = 0; j < 4; j++) {
        int i = t + j * 128, row = i >> 3, g = i & 7;
        ga[j] = *(const uint4*)(A + (size_t)(brow + row) * D_ + g * 8);
        gb[j] = *(const uint4*)(B + (size_t)(bcol + row) * D_ + g * 8);
    }

    for (int kc = 0; kc < D_ / KC_; kc++) {
#pragma unroll
        for (int j = 0; j < 4; j++) {
            int i = t + j * 128, row = i >> 3, g = i & 7;
            *(uint4*)(As + sw_off(row, g)) = ga[j];
            *(uint4*)(Bs + sw_off(row, g)) = gb[j];
        }
        __syncthreads();

        if (kc + 1 < D_ / KC_) {
            int co = (kc + 1) * KC_;
#pragma unroll
            for (int j = 0; j < 4; j++) {
                int i = t + j * 128, row = i >> 3, g = i & 7;
                ga[j] = *(const uint4*)(A + (size_t)(brow + row) * D_ + co + g * 8);
                gb[j] = *(const uint4*)(B + (size_t)(bcol + row) * D_ + co + g * 8);
            }
        }

#pragma unroll
        for (int kh = 0; kh < 4; kh++) {
            unsigned af[2][4], bfr[2][4];
#pragma unroll
            for (int mt = 0; mt < 2; mt++) {
                unsigned ad = asb + sw_off(wr * 32 + mt * 16 + rsel, kh * 2 + gsel);
                asm volatile("ldmatrix.sync.aligned.m8n8.x4.shared.b16 {%0,%1,%2,%3}, [%4];"
                             : "=r"(af[mt][0]), "=r"(af[mt][1]), "=r"(af[mt][2]), "=r"(af[mt][3])
                             : "r"(ad));
            }
#pragma unroll
            for (int np = 0; np < 2; np++) {
                unsigned bd = bsb + sw_off(wc * 32 + np * 16 + rsel, kh * 2 + gsel);
                asm volatile("ldmatrix.sync.aligned.m8n8.x4.shared.b16 {%0,%1,%2,%3}, [%4];"
                             : "=r"(bfr[np][0]), "=r"(bfr[np][1]), "=r"(bfr[np][2]), "=r"(bfr[np][3])
                             : "r"(bd));
            }
#pragma unroll
            for (int mt = 0; mt < 2; mt++)
#pragma unroll
                for (int nt = 0; nt < 4; nt++) {
                    int np = nt >> 1, s = nt & 1;
                    asm volatile(
                        "mma.sync.aligned.m16n8k16.row.col.f32.bf16.bf16.f32 "
                        "{%0,%1,%2,%3},{%4,%5,%6,%7},{%8,%9},{%0,%1,%2,%3};"
                        : "+f"(acc[mt][nt][0]), "+f"(acc[mt][nt][1]),
                          "+f"(acc[mt][nt][2]), "+f"(acc[mt][nt][3])
                        : "r"(af[mt][0]), "r"(af[mt][1]), "r"(af[mt][2]), "r"(af[mt][3]),
                          "r"(bfr[np][0 + s]), "r"(bfr[np][2 + s]));
                }
        }
        __syncthreads();
    }

    // ---- fused epilogue: per-row sum of exp(2*dot) + diagonal dots ----
#pragma unroll
    for (int mt = 0; mt < 2; mt++) {
        float s0 = 0.f, s1 = 0.f;
#pragma unroll
        for (int nt = 0; nt < 4; nt++) {
            s0 += __expf(2.f * acc[mt][nt][0]) + __expf(2.f * acc[mt][nt][1]);
            s1 += __expf(2.f * acc[mt][nt][2]) + __expf(2.f * acc[mt][nt][3]);
        }
        s0 += __shfl_xor_sync(0xffffffffu, s0, 1);
        s0 += __shfl_xor_sync(0xffffffffu, s0, 2);
        s1 += __shfl_xor_sync(0xffffffffu, s1, 1);
        s1 += __shfl_xor_sync(0xffffffffu, s1, 2);
        if ((lane & 3) == 0) {
            int r0 = brow + wr * 32 + mt * 16 + (lane >> 2);
            atomicAdd(&g_expsum[p][r0],     s0);
            atomicAdd(&g_expsum[p][r0 + 8], s1);
        }
    }
    if (brow == bcol) {
        float dsum = 0.f;
#pragma unroll
        for (int mt = 0; mt < 2; mt++)
#pragma unroll
            for (int nt = 0; nt < 4; nt++) {
                int gr = brow + wr * 32 + mt * 16 + (lane >> 2);
                int gc = bcol + wc * 32 + nt * 8 + (lane & 3) * 2;
                if (gr == gc)         dsum += acc[mt][nt][0];
                if (gc + 1 == gr)     dsum += acc[mt][nt][1];
                if (gr + 8 == gc)     dsum += acc[mt][nt][2];
                if (gc + 1 == gr + 8) dsum += acc[mt][nt][3];
            }
        if (dsum != 0.f) atomicAdd(&g_sumdiag, dsum);
    }
}

// ---------------- kernel 3: final scalar (1 block, 512) --------------------
__global__ void __launch_bounds__(512) k3_final(float* __restrict__ out) {
    int t = threadIdx.x;
    float L = __logf(g_expsum[0][t]) + __logf(g_expsum[1][t]) + __logf(g_expsum[2][t]);
    __shared__ float w1[16];
    L = warpSum(L);
    if ((t & 31) == 0) w1[t >> 5] = L;
    __syncthreads();
    if (t == 0) {
        float S = 0.f;
        for (int i = 0; i < 16; i++) S += w1[i];
        // loss_intra = 6 - (2/N)*sum||s||
        // loss_inter = (sum log S_r - 2*sum diag) / P
        out[0] = 6.f - g_sumnorm / 4096.f + (S - 2.f * g_sumdiag) / 512.f;
    }
}

// ---------------- launch ----------------------------------------------------
extern "C" void kernel_launch(void* const* d_in, const int* in_sizes, int n_in,
                              void* d_out, int out_size) {
    const float* fv    = (const float*)d_in[0];
    const float* fa    = (const float*)d_in[1];
    const float* fr    = (const float*)d_in[2];
    const int*   label = (const int*)d_in[3];
    (void)in_sizes; (void)n_in; (void)out_size;

    k0a_hist<<<NB_, 512>>>(label);
    k0b_scan<<<1, 512>>>();
    k0c_fill<<<NB_, 512>>>(label);
    k1_centers<<<dim3(P_, 3), 256>>>(fv, fa, fr);
    k2_gemm<<<dim3(8, 8, 3), 128>>>();
    k3_final<<<1, 512>>>((float*)d_out);
}